// round 9
// baseline (speedup 1.0000x reference)
#include <cuda_runtime.h>
#include <cuda_bf16.h>
#include <cstdint>

#define N_NODES  100000
#define N_PAD    100096   // 782 * 128
#define N_EDGES  400000
#define N_GRAPHS 256
#define HID      256
#define LAYERS   3

typedef __nv_bfloat16 bf16;

// ---------------- static device scratch (allocation-free rule) ----------------
__device__ float d_t  [(size_t)N_EDGES * HID];   // edge MLP stage-1 out (fp32)
__device__ float d_e  [(size_t)N_EDGES * HID];   // final edge embeddings (fp32)
__device__ float d_h  [(size_t)N_PAD   * HID];   // node features
__device__ float d_agg[(size_t)N_PAD   * HID];   // message aggregation
__device__ float d_t2 [(size_t)N_PAD   * HID];   // hidden after conv GEMM1
__device__ bf16  d_Wp [7 * 256 * 512];           // weights, n-major, [hi(256)|lo(256)]
__device__ float d_Wc [4 * HID];                 // We @ W1
__device__ float d_bc [HID];                     // be @ W1 + b1
__device__ float d_bvec[HID];                    // head bias incl. bio part
__device__ float d_gm [N_GRAPHS * HID];          // pooled graph means
__device__ int   d_off[N_GRAPHS + 1];            // per-graph node ranges

// ---------------- helpers ----------------
__device__ __forceinline__ void bsplit(float v, float& h, float& l) {
    bf16 hb = __float2bfloat16(v);
    h = __bfloat162float(hb);
    l = v - h;
}
__device__ __forceinline__ unsigned bfpack(float a, float b) {
    __nv_bfloat162 t = __floats2bfloat162_rn(a, b);
    return *reinterpret_cast<unsigned*>(&t);
}
__device__ __forceinline__ void cp16(bf16* dst, const bf16* src) {
    unsigned d = (unsigned)__cvta_generic_to_shared(dst);
    asm volatile("cp.async.cg.shared.global [%0], [%1], 16;" :: "r"(d), "l"(src));
}

// ---------------- precompute: Wc = We@W1, bc = be@W1+b1, bvec = hb1 + bio@hW1[256:] ----
__global__ void k_pre(const float* __restrict__ We, const float* __restrict__ be,
                      const float* __restrict__ W1, const float* __restrict__ b1,
                      const float* __restrict__ bio, const float* __restrict__ hW1,
                      const float* __restrict__ hb1)
{
    int n = threadIdx.x;
    float s0 = 0.f, s1 = 0.f, s2 = 0.f, s3 = 0.f, sb = 0.f;
    for (int k = 0; k < 256; ++k) {
        float w = W1[k * 256 + n];
        s0 = fmaf(We[k],       w, s0);
        s1 = fmaf(We[256 + k], w, s1);
        s2 = fmaf(We[512 + k], w, s2);
        s3 = fmaf(We[768 + k], w, s3);
        sb = fmaf(be[k],       w, sb);
    }
    d_Wc[n] = s0; d_Wc[256 + n] = s1; d_Wc[512 + n] = s2; d_Wc[768 + n] = s3;
    d_bc[n] = sb + b1[n];
    float t = hb1[n];
    for (int j = 0; j < 512; ++j)
        t = fmaf(bio[j], hW1[(size_t)(256 + j) * 256 + n], t);
    d_bvec[n] = t;
}

// ---------------- weight convert: W [256k,256n] fp32 -> Wp [256n][hi(256)|lo(256)] bf16 ----
__global__ void k_wcvt(const float* __restrict__ W, bf16* __restrict__ Wp)
{
    int id = blockIdx.x * 256 + threadIdx.x;   // 65536
    int k = id >> 8, n = id & 255;
    float v = W[id];
    float hf, lf; bsplit(v, hf, lf);
    Wp[(size_t)n * 512 + k]       = __float2bfloat16(hf);
    Wp[(size_t)n * 512 + 256 + k] = __float2bfloat16(lf);
}

// ---------------- per-graph offsets via binary search (batch is sorted) ----------------
__global__ void k_off(const int* __restrict__ batch)
{
    int g = threadIdx.x;
    if (g > N_GRAPHS) return;
    if (g == N_GRAPHS) { d_off[N_GRAPHS] = N_NODES; return; }
    int lo = 0, hi = N_NODES;
    while (lo < hi) {
        int mid = (lo + hi) >> 1;
        if (batch[mid] < g) lo = mid + 1; else hi = mid;
    }
    d_off[g] = lo;
}

// ---------------- node embedding gather (pad rows -> 0) ----------------
__global__ void k_embed(const int* __restrict__ x, const float* __restrict__ Wn,
                        float* __restrict__ h)
{
    int gid = blockIdx.x * 256 + threadIdx.x;
    int n = gid >> 6;
    int c4 = (gid & 63) << 2;
    float4 v = make_float4(0.f, 0.f, 0.f, 0.f);
    if (n < N_NODES) v = *(const float4*)&Wn[(size_t)x[n] * 256 + c4];
    *(float4*)&h[(size_t)n * 256 + c4] = v;
}

// ---------------- edge stage 1: t = relu(attr @ Wc + bc)  (fp32 out) ----------------
__global__ void k_edge1(const float* __restrict__ attr, float* __restrict__ t)
{
    int gid = blockIdx.x * 256 + threadIdx.x;
    int e = gid >> 6;
    int c4 = (gid & 63) << 2;
    float4 a  = *(const float4*)&attr[(size_t)e * 4];
    float4 w0 = *(const float4*)&d_Wc[c4];
    float4 w1 = *(const float4*)&d_Wc[256 + c4];
    float4 w2 = *(const float4*)&d_Wc[512 + c4];
    float4 w3 = *(const float4*)&d_Wc[768 + c4];
    float4 b  = *(const float4*)&d_bc[c4];
    float4 o;
    o.x = fmaxf(b.x + a.x * w0.x + a.y * w1.x + a.z * w2.x + a.w * w3.x, 0.f);
    o.y = fmaxf(b.y + a.x * w0.y + a.y * w1.y + a.z * w2.y + a.w * w3.y, 0.f);
    o.z = fmaxf(b.z + a.x * w0.z + a.y * w1.z + a.z * w2.z + a.w * w3.z, 0.f);
    o.w = fmaxf(b.w + a.x * w0.w + a.y * w1.w + a.z * w2.w + a.w * w3.w, 0.f);
    *(float4*)&t[(size_t)e * 256 + c4] = o;
}

// ---------------- scatter: agg[dst] += relu(h[src] + e)  (v4 float atomics) ----------------
__global__ void k_scatter(const int* __restrict__ ei, const float* __restrict__ e,
                          const float* __restrict__ h, float* __restrict__ agg)
{
    int gid = blockIdx.x * 256 + threadIdx.x;
    int eid = gid >> 6;
    int c4 = (gid & 63) << 2;
    int src = ei[eid];
    int dst = ei[N_EDGES + eid];
    float4 hv = *(const float4*)&h[(size_t)src * 256 + c4];
    float4 ev = *(const float4*)&e[(size_t)eid * 256 + c4];
    float4 m;
    m.x = fmaxf(hv.x + ev.x, 0.f);
    m.y = fmaxf(hv.y + ev.y, 0.f);
    m.z = fmaxf(hv.z + ev.z, 0.f);
    m.w = fmaxf(hv.w + ev.w, 0.f);
    float* p = &agg[(size_t)dst * 256 + c4];
    asm volatile("red.global.add.v4.f32 [%0], {%1, %2, %3, %4};"
                 :: "l"(p), "f"(m.x), "f"(m.y), "f"(m.z), "f"(m.w) : "memory");
}

// ======================================================================
// bf16 HMMA GEMM with fused fp32 -> (hi,lo) split in the load stage.
//   C[M,256] = epi(A[M,256] @ W^T + bias),  exact-triple: hi*hi + lo*hi + hi*lo
// A fp32 (ALOAD=1: A=(1+eps)*A + Aagg fused on load).
// Wp: [256n][hi(256)|lo(256)] bf16.
// EPI: 0 none; 1 relu; 2 struct scale. All outputs fp32.
// Tile 128x128, 256 thr, dynamic smem 80KB: 2 bufs x {Ah, Al, Bh, Bl}[128][40].
// grid = (2, M/128): n-half fastest so A tiles get L2 reuse.
// ======================================================================
#define TSTR 40
#define TSZ  (128 * TSTR)
#define SMEMB (2 * 4 * TSZ * 2)   // bytes = 81920

template<int ALOAD, int EPI>
__global__ __launch_bounds__(256, 2)
void gemm_bf2(const float* __restrict__ A, const float* __restrict__ Aagg,
              const float* __restrict__ epsp,
              const bf16* __restrict__ Wp, const float* __restrict__ bias,
              const float* __restrict__ eattr, const float* __restrict__ sscale,
              float* __restrict__ C)
{
    extern __shared__ __align__(16) bf16 sm[];
    // layout: buf (2) x mat (0=Ah,1=Al,2=Bh,3=Bl) x [128][TSTR]
    const int tid  = threadIdx.x;
    const int wid  = tid >> 5, lane = tid & 31;
    const int wm   = wid >> 2, wn = wid & 3;      // 2 x 4 warps, warp tile 64x32
    const int g    = lane >> 2, q = lane & 3;
    const int n0   = blockIdx.x * 128;
    const size_t m0 = (size_t)blockIdx.y * 128;

    const int lrow = tid >> 1;          // 0..127
    const int c0   = (tid & 1) * 16;    // 0 or 16

    float epsv = 1.0f;
    if constexpr (ALOAD == 1) epsv = 1.0f + *epsp;

    const float* Ab = A + (m0 + lrow) * 256 + c0;
    const float* Gb = nullptr;
    if constexpr (ALOAD == 1) Gb = Aagg + (m0 + lrow) * 256 + c0;
    const bf16* Bb = Wp + (size_t)(n0 + lrow) * 512 + c0 / 2;   // c0/2: 0 or 8

    float acc[4][4][4];
#pragma unroll
    for (int mt = 0; mt < 4; ++mt)
#pragma unroll
        for (int nt = 0; nt < 4; ++nt)
#pragma unroll
            for (int i = 0; i < 4; ++i) acc[mt][nt][i] = 0.f;

    float v[16];

    // ---- helpers as lambdas ----
    auto loadA = [&](int klog) {
#pragma unroll
        for (int j = 0; j < 4; ++j) {
            float4 f = *(const float4*)(Ab + klog + 4 * j);
            if constexpr (ALOAD == 1) {
                float4 gv = *(const float4*)(Gb + klog + 4 * j);
                f.x = fmaf(epsv, f.x, gv.x); f.y = fmaf(epsv, f.y, gv.y);
                f.z = fmaf(epsv, f.z, gv.z); f.w = fmaf(epsv, f.w, gv.w);
            }
            v[4 * j] = f.x; v[4 * j + 1] = f.y; v[4 * j + 2] = f.z; v[4 * j + 3] = f.w;
        }
    };
    auto cpB = [&](int klog, int buf) {
        // each thread: 16B of Bh chunk + 16B of Bl chunk (row lrow, cols c0/2 .. +8)
        bf16* dh = sm + (buf * 4 + 2) * TSZ + lrow * TSTR + c0 / 2;
        bf16* dl = sm + (buf * 4 + 3) * TSZ + lrow * TSTR + c0 / 2;
        cp16(dh, Bb + klog);
        cp16(dl, Bb + 256 + klog);
        asm volatile("cp.async.commit_group;");
    };
    // B smem col index = klog-local k/... note: per-thread covers 8 bf16 at col (c0/2)
    // chunk is 32 wide but each thread only does 8 -> need 2 rows' worth? No:
    // 128 rows x 32 cols = 4096 bf16 = 8KB; 256 thr x 16B(8 bf16) = 4KB. Need x2.
    // Handled by second pair below in cpB2.
    auto cpB2 = [&](int klog, int buf) {
        bf16* dh = sm + (buf * 4 + 2) * TSZ + lrow * TSTR + c0 / 2 + 16;
        bf16* dl = sm + (buf * 4 + 3) * TSZ + lrow * TSTR + c0 / 2 + 16;
        cp16(dh, Bb + klog + 16);
        cp16(dl, Bb + 256 + klog + 16);
    };
    auto storeA = [&](int buf) {
        unsigned hp[8], lp[8];
#pragma unroll
        for (int i = 0; i < 8; ++i) {
            float h0, l0, h1, l1;
            bsplit(v[2 * i], h0, l0); bsplit(v[2 * i + 1], h1, l1);
            hp[i] = bfpack(h0, h1); lp[i] = bfpack(l0, l1);
        }
        bf16* ah = sm + (buf * 4 + 0) * TSZ + lrow * TSTR + c0;
        bf16* al = sm + (buf * 4 + 1) * TSZ + lrow * TSTR + c0;
        *(uint4*)ah       = make_uint4(hp[0], hp[1], hp[2], hp[3]);
        *(uint4*)(ah + 8) = make_uint4(hp[4], hp[5], hp[6], hp[7]);
        *(uint4*)al       = make_uint4(lp[0], lp[1], lp[2], lp[3]);
        *(uint4*)(al + 8) = make_uint4(lp[4], lp[5], lp[6], lp[7]);
    };

    // ---- preload iteration 0 ----
    loadA(0);
    cpB(0, 0); cpB2(0, 0);
    storeA(0);
    asm volatile("cp.async.wait_group 0;" ::: "memory");
    __syncthreads();

#pragma unroll 1
    for (int it = 0; it < 8; ++it) {
        const int cur = it & 1, nxt = cur ^ 1;
        if (it < 7) {
            cpB((it + 1) * 32, nxt); cpB2((it + 1) * 32, nxt);
            loadA((it + 1) * 32);
        }
        // ---- mma: 3 sub-passes (Ah,Bh), (Al,Bh), (Ah,Bl) ----
#pragma unroll
        for (int s = 0; s < 3; ++s) {
            const bf16* Abuf = sm + (cur * 4 + (s == 1 ? 1 : 0)) * TSZ;
            const bf16* Bbuf = sm + (cur * 4 + (s == 2 ? 3 : 2)) * TSZ;
#pragma unroll
            for (int ks = 0; ks < 2; ++ks) {
                const int kk = ks * 16;
                unsigned a[4][4], b[4][2];
#pragma unroll
                for (int mt = 0; mt < 4; ++mt) {
                    int r = wm * 64 + mt * 16 + g;
                    a[mt][0] = *(const unsigned*)&Abuf[r * TSTR + kk + 2 * q];
                    a[mt][1] = *(const unsigned*)&Abuf[(r + 8) * TSTR + kk + 2 * q];
                    a[mt][2] = *(const unsigned*)&Abuf[r * TSTR + kk + 2 * q + 8];
                    a[mt][3] = *(const unsigned*)&Abuf[(r + 8) * TSTR + kk + 2 * q + 8];
                }
#pragma unroll
                for (int nt = 0; nt < 4; ++nt) {
                    int c = wn * 32 + nt * 8 + g;
                    b[nt][0] = *(const unsigned*)&Bbuf[c * TSTR + kk + 2 * q];
                    b[nt][1] = *(const unsigned*)&Bbuf[c * TSTR + kk + 2 * q + 8];
                }
#pragma unroll
                for (int mt = 0; mt < 4; ++mt)
#pragma unroll
                    for (int nt = 0; nt < 4; ++nt)
                        asm volatile(
                            "mma.sync.aligned.m16n8k16.row.col.f32.bf16.bf16.f32 "
                            "{%0,%1,%2,%3}, {%4,%5,%6,%7}, {%8,%9}, {%0,%1,%2,%3};"
                            : "+f"(acc[mt][nt][0]), "+f"(acc[mt][nt][1]),
                              "+f"(acc[mt][nt][2]), "+f"(acc[mt][nt][3])
                            : "r"(a[mt][0]), "r"(a[mt][1]), "r"(a[mt][2]), "r"(a[mt][3]),
                              "r"(b[nt][0]), "r"(b[nt][1]));
            }
        }
        if (it < 7) {
            storeA(nxt);
            asm volatile("cp.async.wait_group 0;" ::: "memory");
        }
        __syncthreads();
    }

    // ---- epilogue ----
    const float sval = (EPI == 2) ? *sscale : 1.f;
#pragma unroll
    for (int mt = 0; mt < 4; ++mt) {
        size_t r0 = m0 + wm * 64 + mt * 16 + g;
        size_t r1 = r0 + 8;
        float s0 = 1.f, s1 = 1.f;
        if (EPI == 2) {
            s0 = (eattr[r0 * 4 + 1] > 0.f) ? sval : 1.f;
            s1 = (eattr[r1 * 4 + 1] > 0.f) ? sval : 1.f;
        }
#pragma unroll
        for (int nt = 0; nt < 4; ++nt) {
            int c = n0 + wn * 32 + nt * 8 + 2 * q;
            float b0 = bias[c], b1 = bias[c + 1];
            float v00 = acc[mt][nt][0] + b0;
            float v01 = acc[mt][nt][1] + b1;
            float v10 = acc[mt][nt][2] + b0;
            float v11 = acc[mt][nt][3] + b1;
            if (EPI == 1) {
                v00 = fmaxf(v00, 0.f); v01 = fmaxf(v01, 0.f);
                v10 = fmaxf(v10, 0.f); v11 = fmaxf(v11, 0.f);
            } else if (EPI == 2) {
                v00 *= s0; v01 *= s0; v10 *= s1; v11 *= s1;
            }
            *(float2*)&C[r0 * 256 + c] = make_float2(v00, v01);
            *(float2*)&C[r1 * 256 + c] = make_float2(v10, v11);
        }
    }
}

// ---------------- GraphNorm (in place), optional pooled-mean emit ----------------
__global__ void k_gnorm(float* __restrict__ h, const float* __restrict__ gamma,
                        const float* __restrict__ beta, const float* __restrict__ alpha,
                        int last)
{
    int g = blockIdx.x, c = threadIdx.x;
    int s = d_off[g], e = d_off[g + 1];
    int cnt = e - s;
    float inv = 1.0f / (float)(cnt > 0 ? cnt : 1);

    float mean = 0.f;
    for (int n = s; n < e; ++n) mean += h[(size_t)n * 256 + c];
    mean *= inv;
    float am = alpha[c] * mean;

    float var = 0.f;
    for (int n = s; n < e; ++n) {
        float dd = h[(size_t)n * 256 + c] - am;
        var = fmaf(dd, dd, var);
    }
    var *= inv;

    float sc = gamma[c] * rsqrtf(var + 1e-5f);
    float bt = beta[c];
    float gs = 0.f;
    for (int n = s; n < e; ++n) {
        float o = (h[(size_t)n * 256 + c] - am) * sc + bt;
        h[(size_t)n * 256 + c] = o;
        gs += o;
    }
    if (last) d_gm[g * 256 + c] = gs * inv;
}

// ---------------- head: out[g] = relu([g_mean, bio] @ W1 + b1) @ W2 + b2 ----------------
__global__ void k_head(const float* __restrict__ W1, const float* __restrict__ W2,
                       const float* __restrict__ b2, float* __restrict__ out)
{
    __shared__ float gs[256];
    __shared__ float red[256];
    int g = blockIdx.x, n = threadIdx.x;
    gs[n] = d_gm[g * 256 + n];
    __syncthreads();
    float s = d_bvec[n];
#pragma unroll 8
    for (int k = 0; k < 256; ++k)
        s = fmaf(gs[k], W1[(size_t)k * 256 + n], s);
    red[n] = fmaxf(s, 0.f) * W2[n];
    __syncthreads();
    for (int st = 128; st > 0; st >>= 1) {
        if (n < st) red[n] += red[n + st];
        __syncthreads();
    }
    if (n == 0) out[g] = red[0] + b2[0];
}

// ---------------- launch ----------------
extern "C" void kernel_launch(void* const* d_in, const int* in_sizes, int n_in,
                              void* d_out, int out_size)
{
    const int*   x     = (const int*)d_in[0];
    const int*   ei    = (const int*)d_in[1];
    const float* attr  = (const float*)d_in[2];
    const int*   batch = (const int*)d_in[3];
    const float* nodeW = (const float*)d_in[4];
    const float* eW    = (const float*)d_in[5];
    const float* eb    = (const float*)d_in[6];
    const float* mW1   = (const float*)d_in[7];
    const float* mb1   = (const float*)d_in[8];
    const float* mW2   = (const float*)d_in[9];
    const float* mb2   = (const float*)d_in[10];
    const float* ss    = (const float*)d_in[11];
    const float* cW1   = (const float*)d_in[12];
    const float* cb1   = (const float*)d_in[13];
    const float* cW2   = (const float*)d_in[14];
    const float* cb2   = (const float*)d_in[15];
    const float* ceps  = (const float*)d_in[16];
    const float* ngam  = (const float*)d_in[17];
    const float* nbet  = (const float*)d_in[18];
    const float* nalp  = (const float*)d_in[19];
    const float* bio   = (const float*)d_in[20];
    const float* hW1   = (const float*)d_in[21];
    const float* hb1   = (const float*)d_in[22];
    const float* hW2   = (const float*)d_in[23];
    const float* hb2   = (const float*)d_in[24];
    float* out = (float*)d_out;

    float *t, *e, *h, *agg, *t2;
    bf16 *Wp;
    cudaGetSymbolAddress((void**)&t,   d_t);
    cudaGetSymbolAddress((void**)&e,   d_e);
    cudaGetSymbolAddress((void**)&h,   d_h);
    cudaGetSymbolAddress((void**)&agg, d_agg);
    cudaGetSymbolAddress((void**)&t2,  d_t2);
    cudaGetSymbolAddress((void**)&Wp,  d_Wp);

    cudaFuncSetAttribute(gemm_bf2<0,2>, cudaFuncAttributeMaxDynamicSharedMemorySize, SMEMB);
    cudaFuncSetAttribute(gemm_bf2<1,1>, cudaFuncAttributeMaxDynamicSharedMemorySize, SMEMB);
    cudaFuncSetAttribute(gemm_bf2<0,0>, cudaFuncAttributeMaxDynamicSharedMemorySize, SMEMB);

    const size_t WSTRIDE = (size_t)256 * 512;

    k_pre<<<1, 256>>>(eW, eb, mW1, mb1, bio, hW1, hb1);
    k_off<<<1, N_GRAPHS + 1>>>(batch);
    k_wcvt<<<256, 256>>>(mW2, Wp);                       // slot 0: edge MLP W2
    for (int l = 0; l < LAYERS; ++l) {
        k_wcvt<<<256, 256>>>(cW1 + (size_t)l * 65536, Wp + (1 + l) * WSTRIDE);
        k_wcvt<<<256, 256>>>(cW2 + (size_t)l * 65536, Wp + (4 + l) * WSTRIDE);
    }
    k_embed<<<N_PAD / 4, 256>>>(x, nodeW, h);
    k_edge1<<<N_EDGES / 4, 256>>>(attr, t);

    gemm_bf2<0,2><<<dim3(2, N_EDGES / 128), 256, SMEMB>>>(
        t, nullptr, nullptr, Wp, mb2, attr, ss, e);

    for (int l = 0; l < LAYERS; ++l) {
        cudaMemsetAsync(agg, 0, (size_t)N_PAD * 256 * sizeof(float), 0);
        k_scatter<<<N_EDGES / 4, 256>>>(ei, e, h, agg);
        gemm_bf2<1,1><<<dim3(2, N_PAD / 128), 256, SMEMB>>>(
            h, agg, ceps + l, Wp + (1 + l) * WSTRIDE, cb1 + (size_t)l * 256,
            nullptr, nullptr, t2);
        gemm_bf2<0,0><<<dim3(2, N_PAD / 128), 256, SMEMB>>>(
            t2, nullptr, nullptr, Wp + (4 + l) * WSTRIDE, cb2 + (size_t)l * 256,
            nullptr, nullptr, h);
        k_gnorm<<<N_GRAPHS, 256>>>(h, ngam + (size_t)l * 256, nbet + (size_t)l * 256,
                                   nalp + (size_t)l * 256, l == LAYERS - 1);
    }
    k_head<<<N_GRAPHS, 256>>>(hW1, hW2, hb2, out);
}

// round 13
// speedup vs baseline: 1.4002x; 1.4002x over previous
#include <cuda_runtime.h>
#include <cuda_bf16.h>
#include <cstdint>

#define N_NODES  100000
#define N_PAD    100096   // 782 * 128
#define N_EDGES  400000
#define N_GRAPHS 256
#define HID      256
#define LAYERS   3

typedef __nv_bfloat16 bf16;

// ---------------- static device scratch (allocation-free rule) ----------------
__device__ float d_e  [(size_t)N_EDGES * HID];   // final edge embeddings (fp32)
__device__ float d_h  [(size_t)N_PAD   * HID];   // node features
__device__ float d_agg[(size_t)N_PAD   * HID];   // message aggregation
__device__ float d_t2 [(size_t)N_PAD   * HID];   // hidden after conv GEMM1
__device__ bf16  d_Wp [7 * 256 * 512];           // weights, n-major, [hi(256)|lo(256)]
__device__ float d_Wc [4 * HID];                 // We @ W1
__device__ float d_bc [HID];                     // be @ W1 + b1
__device__ float d_bvec[HID];                    // head bias incl. bio part
__device__ float d_gm [N_GRAPHS * HID];          // pooled graph means
__device__ int   d_off[N_GRAPHS + 1];            // per-graph node ranges

// ---------------- helpers ----------------
__device__ __forceinline__ void bsplit(float v, float& h, float& l) {
    bf16 hb = __float2bfloat16(v);
    h = __bfloat162float(hb);
    l = v - h;
}
__device__ __forceinline__ unsigned bfpack(float a, float b) {
    __nv_bfloat162 t = __floats2bfloat162_rn(a, b);
    return *reinterpret_cast<unsigned*>(&t);
}
__device__ __forceinline__ void cp16(bf16* dst, const bf16* src) {
    unsigned d = (unsigned)__cvta_generic_to_shared(dst);
    asm volatile("cp.async.cg.shared.global [%0], [%1], 16;" :: "r"(d), "l"(src));
}

// ---------------- precompute: Wc = We@W1, bc = be@W1+b1, bvec = hb1 + bio@hW1[256:] ----
__global__ void k_pre(const float* __restrict__ We, const float* __restrict__ be,
                      const float* __restrict__ W1, const float* __restrict__ b1,
                      const float* __restrict__ bio, const float* __restrict__ hW1,
                      const float* __restrict__ hb1)
{
    int n = threadIdx.x;
    float s0 = 0.f, s1 = 0.f, s2 = 0.f, s3 = 0.f, sb = 0.f;
    for (int k = 0; k < 256; ++k) {
        float w = W1[k * 256 + n];
        s0 = fmaf(We[k],       w, s0);
        s1 = fmaf(We[256 + k], w, s1);
        s2 = fmaf(We[512 + k], w, s2);
        s3 = fmaf(We[768 + k], w, s3);
        sb = fmaf(be[k],       w, sb);
    }
    d_Wc[n] = s0; d_Wc[256 + n] = s1; d_Wc[512 + n] = s2; d_Wc[768 + n] = s3;
    d_bc[n] = sb + b1[n];
    float t = hb1[n];
    for (int j = 0; j < 512; ++j)
        t = fmaf(bio[j], hW1[(size_t)(256 + j) * 256 + n], t);
    d_bvec[n] = t;
}

// ---------------- weight convert: W [256k,256n] fp32 -> Wp [256n][hi(256)|lo(256)] bf16 ----
__global__ void k_wcvt(const float* __restrict__ W, bf16* __restrict__ Wp)
{
    int id = blockIdx.x * 256 + threadIdx.x;   // 65536
    int k = id >> 8, n = id & 255;
    float v = W[id];
    float hf, lf; bsplit(v, hf, lf);
    Wp[(size_t)n * 512 + k]       = __float2bfloat16(hf);
    Wp[(size_t)n * 512 + 256 + k] = __float2bfloat16(lf);
}

// ---------------- per-graph offsets via binary search (batch is sorted) ----------------
__global__ void k_off(const int* __restrict__ batch)
{
    int g = threadIdx.x;
    if (g > N_GRAPHS) return;
    if (g == N_GRAPHS) { d_off[N_GRAPHS] = N_NODES; return; }
    int lo = 0, hi = N_NODES;
    while (lo < hi) {
        int mid = (lo + hi) >> 1;
        if (batch[mid] < g) lo = mid + 1; else hi = mid;
    }
    d_off[g] = lo;
}

// ---------------- node embedding gather (pad rows -> 0) ----------------
__global__ void k_embed(const int* __restrict__ x, const float* __restrict__ Wn,
                        float* __restrict__ h)
{
    int gid = blockIdx.x * 256 + threadIdx.x;
    int n = gid >> 6;
    int c4 = (gid & 63) << 2;
    float4 v = make_float4(0.f, 0.f, 0.f, 0.f);
    if (n < N_NODES) v = *(const float4*)&Wn[(size_t)x[n] * 256 + c4];
    *(float4*)&h[(size_t)n * 256 + c4] = v;
}

// ---------------- scatter: agg[dst] += relu(h[src] + e)  (v4 float atomics) ----------------
__global__ void k_scatter(const int* __restrict__ ei, const float* __restrict__ e,
                          const float* __restrict__ h, float* __restrict__ agg)
{
    int gid = blockIdx.x * 256 + threadIdx.x;
    int eid = gid >> 6;
    int c4 = (gid & 63) << 2;
    int src = ei[eid];
    int dst = ei[N_EDGES + eid];
    float4 hv = *(const float4*)&h[(size_t)src * 256 + c4];
    float4 ev = *(const float4*)&e[(size_t)eid * 256 + c4];
    float4 m;
    m.x = fmaxf(hv.x + ev.x, 0.f);
    m.y = fmaxf(hv.y + ev.y, 0.f);
    m.z = fmaxf(hv.z + ev.z, 0.f);
    m.w = fmaxf(hv.w + ev.w, 0.f);
    float* p = &agg[(size_t)dst * 256 + c4];
    asm volatile("red.global.add.v4.f32 [%0], {%1, %2, %3, %4};"
                 :: "l"(p), "f"(m.x), "f"(m.y), "f"(m.z), "f"(m.w) : "memory");
}

// ======================================================================
// bf16 HMMA GEMM with fused fp32->(hi,lo) split at SMEM staging.
//   C[M,64-chunk] = epi(Arow @ W^T + bias), exact triple: hi*hi + lo*hi + hi*lo
// ALOAD: 0 plain fp32 A; 1 A=(1+eps)*A+Aagg (GINE); 2 A row = relu(attr@Wc+bc).
// EPI:   0 none; 1 relu; 2 struct scale. Output fp32.
// CTA tile 128(M) x 64(N), BK=32, 256 thr, 8 warps (4x2) warp tile 32x32.
// grid = (4 n-chunks fastest, M/128) -> A tile L2 reuse across 4 CTAs.
// ======================================================================
#define TSTR 40
#define ATS  (128 * TSTR)          // A tile elems (bf16)
#define BTS  (64 * TSTR)           // B tile elems
#define SSTG (2 * ATS + 2 * BTS)   // elems per stage buffer
#define SMEMB (2 * SSTG * 2 + 5120)  // 2 bufs *2B + Wc/bc fp32 region = 66560

template<int ALOAD, int EPI>
__global__ __launch_bounds__(256, 2)
void gemm_bf3(const float* __restrict__ A, const float* __restrict__ Aagg,
              const float* __restrict__ epsp,
              const bf16* __restrict__ Wp, const float* __restrict__ bias,
              const float* __restrict__ eattr, const float* __restrict__ sscale,
              float* __restrict__ C)
{
    extern __shared__ __align__(16) bf16 sm[];
    float* smF = (float*)(sm + 2 * SSTG);   // Wc (1024) + bc (256) for ALOAD==2

    const int tid  = threadIdx.x;
    const int wid  = tid >> 5, lane = tid & 31;
    const int wm   = wid >> 1, wn = wid & 1;      // 4 x 2 warps, warp tile 32x32
    const int g    = lane >> 2, q = lane & 3;
    const int n0   = blockIdx.x * 64;
    const size_t m0 = (size_t)blockIdx.y * 128;

    const int lrow = tid >> 1;          // 0..127  (A staging row)
    const int c0   = (tid & 1) * 16;    // 0 or 16 (A staging col)
    const int brow = tid >> 2;          // 0..63   (B staging row)
    const int bcol = (tid & 3) * 8;     // 0,8,16,24

    float epsv = 1.0f;
    if constexpr (ALOAD == 1) epsv = 1.0f + *epsp;

    float at0 = 0.f, at1 = 0.f, at2 = 0.f, at3 = 0.f;
    if constexpr (ALOAD == 2) {
        // stage Wc (4x256) + bc (256) into smem once
        for (int i = tid; i < 1280; i += 256)
            smF[i] = (i < 1024) ? d_Wc[i] : d_bc[i - 1024];
        float4 av = *(const float4*)(A + (m0 + lrow) * 4);   // A == attr here
        at0 = av.x; at1 = av.y; at2 = av.z; at3 = av.w;
        __syncthreads();
    }

    const float* Ab = A + (m0 + lrow) * 256 + c0;
    const float* Gb = nullptr;
    if constexpr (ALOAD == 1) Gb = Aagg + (m0 + lrow) * 256 + c0;
    const bf16* Bb = Wp + (size_t)(n0 + brow) * 512 + bcol;

    float acc[2][4][4];
#pragma unroll
    for (int mt = 0; mt < 2; ++mt)
#pragma unroll
        for (int nt = 0; nt < 4; ++nt)
#pragma unroll
            for (int i = 0; i < 4; ++i) acc[mt][nt][i] = 0.f;

    float v[16];

    auto loadA = [&](int klog) {
        if constexpr (ALOAD == 2) {
#pragma unroll
            for (int j = 0; j < 16; ++j) {
                int col = klog + c0 + j;
                float s = smF[1024 + col];
                s = fmaf(at0, smF[col],       s);
                s = fmaf(at1, smF[256 + col], s);
                s = fmaf(at2, smF[512 + col], s);
                s = fmaf(at3, smF[768 + col], s);
                v[j] = fmaxf(s, 0.f);
            }
        } else {
#pragma unroll
            for (int j = 0; j < 4; ++j) {
                float4 f = *(const float4*)(Ab + klog + 4 * j);
                if constexpr (ALOAD == 1) {
                    float4 gv = *(const float4*)(Gb + klog + 4 * j);
                    f.x = fmaf(epsv, f.x, gv.x); f.y = fmaf(epsv, f.y, gv.y);
                    f.z = fmaf(epsv, f.z, gv.z); f.w = fmaf(epsv, f.w, gv.w);
                }
                v[4 * j] = f.x; v[4 * j + 1] = f.y; v[4 * j + 2] = f.z; v[4 * j + 3] = f.w;
            }
        }
    };
    auto cpB = [&](int klog, int buf) {
        bf16* base = sm + buf * SSTG + 2 * ATS;
        cp16(base + brow * TSTR + bcol,       Bb + klog);          // Bh
        cp16(base + BTS + brow * TSTR + bcol, Bb + 256 + klog);    // Bl
        asm volatile("cp.async.commit_group;");
    };
    auto storeA = [&](int buf) {
        unsigned hp[8], lp[8];
#pragma unroll
        for (int i = 0; i < 8; ++i) {
            float h0, l0, h1, l1;
            bsplit(v[2 * i], h0, l0); bsplit(v[2 * i + 1], h1, l1);
            hp[i] = bfpack(h0, h1); lp[i] = bfpack(l0, l1);
        }
        bf16* ah = sm + buf * SSTG + lrow * TSTR + c0;
        bf16* al = ah + ATS;
        *(uint4*)ah       = make_uint4(hp[0], hp[1], hp[2], hp[3]);
        *(uint4*)(ah + 8) = make_uint4(hp[4], hp[5], hp[6], hp[7]);
        *(uint4*)al       = make_uint4(lp[0], lp[1], lp[2], lp[3]);
        *(uint4*)(al + 8) = make_uint4(lp[4], lp[5], lp[6], lp[7]);
    };

    // ---- prologue: buffer 0 ----
    loadA(0);
    cpB(0, 0);
    storeA(0);
    asm volatile("cp.async.wait_group 0;" ::: "memory");
    __syncthreads();

#pragma unroll 1
    for (int it = 0; it < 8; ++it) {
        const int cur = it & 1, nxt = cur ^ 1;
        if (it < 7) {
            cpB((it + 1) * 32, nxt);
            loadA((it + 1) * 32);
        }
#pragma unroll
        for (int s = 0; s < 3; ++s) {
            const bf16* Abuf = sm + cur * SSTG + (s == 1 ? ATS : 0);
            const bf16* Bbuf = sm + cur * SSTG + 2 * ATS + (s == 2 ? BTS : 0);
#pragma unroll
            for (int ks = 0; ks < 2; ++ks) {
                const int kk = ks * 16;
                unsigned a[2][4], b[4][2];
#pragma unroll
                for (int mt = 0; mt < 2; ++mt) {
                    int r = wm * 32 + mt * 16 + g;
                    a[mt][0] = *(const unsigned*)&Abuf[r * TSTR + kk + 2 * q];
                    a[mt][1] = *(const unsigned*)&Abuf[(r + 8) * TSTR + kk + 2 * q];
                    a[mt][2] = *(const unsigned*)&Abuf[r * TSTR + kk + 2 * q + 8];
                    a[mt][3] = *(const unsigned*)&Abuf[(r + 8) * TSTR + kk + 2 * q + 8];
                }
#pragma unroll
                for (int nt = 0; nt < 4; ++nt) {
                    int c = wn * 32 + nt * 8 + g;
                    b[nt][0] = *(const unsigned*)&Bbuf[c * TSTR + kk + 2 * q];
                    b[nt][1] = *(const unsigned*)&Bbuf[c * TSTR + kk + 2 * q + 8];
                }
#pragma unroll
                for (int mt = 0; mt < 2; ++mt)
#pragma unroll
                    for (int nt = 0; nt < 4; ++nt)
                        asm volatile(
                            "mma.sync.aligned.m16n8k16.row.col.f32.bf16.bf16.f32 "
                            "{%0,%1,%2,%3}, {%4,%5,%6,%7}, {%8,%9}, {%0,%1,%2,%3};"
                            : "+f"(acc[mt][nt][0]), "+f"(acc[mt][nt][1]),
                              "+f"(acc[mt][nt][2]), "+f"(acc[mt][nt][3])
                            : "r"(a[mt][0]), "r"(a[mt][1]), "r"(a[mt][2]), "r"(a[mt][3]),
                              "r"(b[nt][0]), "r"(b[nt][1]));
            }
        }
        if (it < 7) {
            storeA(nxt);
            asm volatile("cp.async.wait_group 0;" ::: "memory");
        }
        __syncthreads();
    }

    // ---- epilogue ----
    const float sval = (EPI == 2) ? *sscale : 1.f;
#pragma unroll
    for (int mt = 0; mt < 2; ++mt) {
        size_t r0 = m0 + wm * 32 + mt * 16 + g;
        size_t r1 = r0 + 8;
        float s0 = 1.f, s1 = 1.f;
        if (EPI == 2) {
            s0 = (eattr[r0 * 4 + 1] > 0.f) ? sval : 1.f;
            s1 = (eattr[r1 * 4 + 1] > 0.f) ? sval : 1.f;
        }
#pragma unroll
        for (int nt = 0; nt < 4; ++nt) {
            int c = n0 + wn * 32 + nt * 8 + 2 * q;
            float b0 = bias[c], b1 = bias[c + 1];
            float v00 = acc[mt][nt][0] + b0;
            float v01 = acc[mt][nt][1] + b1;
            float v10 = acc[mt][nt][2] + b0;
            float v11 = acc[mt][nt][3] + b1;
            if (EPI == 1) {
                v00 = fmaxf(v00, 0.f); v01 = fmaxf(v01, 0.f);
                v10 = fmaxf(v10, 0.f); v11 = fmaxf(v11, 0.f);
            } else if (EPI == 2) {
                v00 *= s0; v01 *= s0; v10 *= s1; v11 *= s1;
            }
            *(float2*)&C[r0 * 256 + c] = make_float2(v00, v01);
            *(float2*)&C[r1 * 256 + c] = make_float2(v10, v11);
        }
    }
}

// ---------------- GraphNorm (in place), optional pooled-mean emit ----------------
__global__ void k_gnorm(float* __restrict__ h, const float* __restrict__ gamma,
                        const float* __restrict__ beta, const float* __restrict__ alpha,
                        int last)
{
    int g = blockIdx.x, c = threadIdx.x;
    int s = d_off[g], e = d_off[g + 1];
    int cnt = e - s;
    float inv = 1.0f / (float)(cnt > 0 ? cnt : 1);

    float mean = 0.f;
    for (int n = s; n < e; ++n) mean += h[(size_t)n * 256 + c];
    mean *= inv;
    float am = alpha[c] * mean;

    float var = 0.f;
    for (int n = s; n < e; ++n) {
        float dd = h[(size_t)n * 256 + c] - am;
        var = fmaf(dd, dd, var);
    }
    var *= inv;

    float sc = gamma[c] * rsqrtf(var + 1e-5f);
    float bt = beta[c];
    float gs = 0.f;
    for (int n = s; n < e; ++n) {
        float o = (h[(size_t)n * 256 + c] - am) * sc + bt;
        h[(size_t)n * 256 + c] = o;
        gs += o;
    }
    if (last) d_gm[g * 256 + c] = gs * inv;
}

// ---------------- head: out[g] = relu([g_mean, bio] @ W1 + b1) @ W2 + b2 ----------------
__global__ void k_head(const float* __restrict__ W1, const float* __restrict__ W2,
                       const float* __restrict__ b2, float* __restrict__ out)
{
    __shared__ float gs[256];
    __shared__ float red[256];
    int g = blockIdx.x, n = threadIdx.x;
    gs[n] = d_gm[g * 256 + n];
    __syncthreads();
    float s = d_bvec[n];
#pragma unroll 8
    for (int k = 0; k < 256; ++k)
        s = fmaf(gs[k], W1[(size_t)k * 256 + n], s);
    red[n] = fmaxf(s, 0.f) * W2[n];
    __syncthreads();
    for (int st = 128; st > 0; st >>= 1) {
        if (n < st) red[n] += red[n + st];
        __syncthreads();
    }
    if (n == 0) out[g] = red[0] + b2[0];
}

// ---------------- launch ----------------
extern "C" void kernel_launch(void* const* d_in, const int* in_sizes, int n_in,
                              void* d_out, int out_size)
{
    const int*   x     = (const int*)d_in[0];
    const int*   ei    = (const int*)d_in[1];
    const float* attr  = (const float*)d_in[2];
    const int*   batch = (const int*)d_in[3];
    const float* nodeW = (const float*)d_in[4];
    const float* eW    = (const float*)d_in[5];
    const float* eb    = (const float*)d_in[6];
    const float* mW1   = (const float*)d_in[7];
    const float* mb1   = (const float*)d_in[8];
    const float* mW2   = (const float*)d_in[9];
    const float* mb2   = (const float*)d_in[10];
    const float* ss    = (const float*)d_in[11];
    const float* cW1   = (const float*)d_in[12];
    const float* cb1   = (const float*)d_in[13];
    const float* cW2   = (const float*)d_in[14];
    const float* cb2   = (const float*)d_in[15];
    const float* ceps  = (const float*)d_in[16];
    const float* ngam  = (const float*)d_in[17];
    const float* nbet  = (const float*)d_in[18];
    const float* nalp  = (const float*)d_in[19];
    const float* bio   = (const float*)d_in[20];
    const float* hW1   = (const float*)d_in[21];
    const float* hb1   = (const float*)d_in[22];
    const float* hW2   = (const float*)d_in[23];
    const float* hb2   = (const float*)d_in[24];
    float* out = (float*)d_out;

    float *e, *h, *agg, *t2;
    bf16 *Wp;
    cudaGetSymbolAddress((void**)&e,   d_e);
    cudaGetSymbolAddress((void**)&h,   d_h);
    cudaGetSymbolAddress((void**)&agg, d_agg);
    cudaGetSymbolAddress((void**)&t2,  d_t2);
    cudaGetSymbolAddress((void**)&Wp,  d_Wp);

    cudaFuncSetAttribute(gemm_bf3<2,2>, cudaFuncAttributeMaxDynamicSharedMemorySize, SMEMB);
    cudaFuncSetAttribute(gemm_bf3<1,1>, cudaFuncAttributeMaxDynamicSharedMemorySize, SMEMB);
    cudaFuncSetAttribute(gemm_bf3<0,0>, cudaFuncAttributeMaxDynamicSharedMemorySize, SMEMB);

    const size_t WSTRIDE = (size_t)256 * 512;

    k_pre<<<1, 256>>>(eW, eb, mW1, mb1, bio, hW1, hb1);
    k_off<<<1, N_GRAPHS + 1>>>(batch);
    k_wcvt<<<256, 256>>>(mW2, Wp);                       // slot 0: edge MLP W2
    for (int l = 0; l < LAYERS; ++l) {
        k_wcvt<<<256, 256>>>(cW1 + (size_t)l * 65536, Wp + (1 + l) * WSTRIDE);
        k_wcvt<<<256, 256>>>(cW2 + (size_t)l * 65536, Wp + (4 + l) * WSTRIDE);
    }
    k_embed<<<N_PAD / 4, 256>>>(x, nodeW, h);

    // edge MLP stage 1 fused into GEMM A-staging (ALOAD=2): A param = attr
    gemm_bf3<2,2><<<dim3(4, N_EDGES / 128), 256, SMEMB>>>(
        attr, nullptr, nullptr, Wp, mb2, attr, ss, e);

    for (int l = 0; l < LAYERS; ++l) {
        cudaMemsetAsync(agg, 0, (size_t)N_PAD * 256 * sizeof(float), 0);
        k_scatter<<<N_EDGES / 4, 256>>>(ei, e, h, agg);
        gemm_bf3<1,1><<<dim3(4, N_PAD / 128), 256, SMEMB>>>(
            h, agg, ceps + l, Wp + (1 + l) * WSTRIDE, cb1 + (size_t)l * 256,
            nullptr, nullptr, t2);
        gemm_bf3<0,0><<<dim3(4, N_PAD / 128), 256, SMEMB>>>(
            t2, nullptr, nullptr, Wp + (4 + l) * WSTRIDE, cb2 + (size_t)l * 256,
            nullptr, nullptr, h);
        k_gnorm<<<N_GRAPHS, 256>>>(h, ngam + (size_t)l * 256, nbet + (size_t)l * 256,
                                   nalp + (size_t)l * 256, l == LAYERS - 1);
    }
    k_head<<<N_GRAPHS, 256>>>(hW1, hW2, hb2, out);
}

// round 15
// speedup vs baseline: 1.4642x; 1.0457x over previous
#include <cuda_runtime.h>
#include <cuda_bf16.h>
#include <cstdint>

#define N_NODES  100000
#define N_PAD    100096   // 782 * 128
#define N_EDGES  400000
#define N_GRAPHS 256
#define HID      256
#define LAYERS   3

typedef __nv_bfloat16 bf16;

// ---------------- static device scratch (allocation-free rule) ----------------
__device__ float d_e  [(size_t)N_EDGES * HID];   // final edge embeddings (fp32)
__device__ float d_h  [(size_t)N_PAD   * HID];   // node features
__device__ float d_agg[(size_t)N_PAD   * HID];   // message aggregation
__device__ float d_t2 [(size_t)N_PAD   * HID];   // hidden after conv GEMM1
__device__ bf16  d_Wp [7 * 256 * 512];           // weights, n-major, [hi(256)|lo(256)]
__device__ float d_Wc [4 * HID];                 // We @ W1
__device__ float d_bc [HID];                     // be @ W1 + b1
__device__ float d_bvec[HID];                    // head bias incl. bio part
__device__ float d_gm [N_GRAPHS * HID];          // pooled graph means
__device__ int   d_off[N_GRAPHS + 1];            // per-graph node ranges

// ---------------- helpers ----------------
__device__ __forceinline__ void bsplit(float v, float& h, float& l) {
    bf16 hb = __float2bfloat16(v);
    h = __bfloat162float(hb);
    l = v - h;
}
__device__ __forceinline__ unsigned bfpack(float a, float b) {
    __nv_bfloat162 t = __floats2bfloat162_rn(a, b);
    return *reinterpret_cast<unsigned*>(&t);
}
__device__ __forceinline__ void cp16(bf16* dst, const bf16* src) {
    unsigned d = (unsigned)__cvta_generic_to_shared(dst);
    asm volatile("cp.async.cg.shared.global [%0], [%1], 16;" :: "r"(d), "l"(src));
}
__device__ __forceinline__ uint4 ldsm4(unsigned addr) {
    uint4 r;
    asm volatile("ldmatrix.sync.aligned.m8n8.x4.shared.b16 {%0,%1,%2,%3}, [%4];"
                 : "=r"(r.x), "=r"(r.y), "=r"(r.z), "=r"(r.w) : "r"(addr));
    return r;
}

// ---------------- precompute: Wc = We@W1, bc = be@W1+b1, bvec = hb1 + bio@hW1[256:] ----
__global__ void k_pre(const float* __restrict__ We, const float* __restrict__ be,
                      const float* __restrict__ W1, const float* __restrict__ b1,
                      const float* __restrict__ bio, const float* __restrict__ hW1,
                      const float* __restrict__ hb1)
{
    int n = threadIdx.x;
    float s0 = 0.f, s1 = 0.f, s2 = 0.f, s3 = 0.f, sb = 0.f;
    for (int k = 0; k < 256; ++k) {
        float w = W1[k * 256 + n];
        s0 = fmaf(We[k],       w, s0);
        s1 = fmaf(We[256 + k], w, s1);
        s2 = fmaf(We[512 + k], w, s2);
        s3 = fmaf(We[768 + k], w, s3);
        sb = fmaf(be[k],       w, sb);
    }
    d_Wc[n] = s0; d_Wc[256 + n] = s1; d_Wc[512 + n] = s2; d_Wc[768 + n] = s3;
    d_bc[n] = sb + b1[n];
    float t = hb1[n];
    for (int j = 0; j < 512; ++j)
        t = fmaf(bio[j], hW1[(size_t)(256 + j) * 256 + n], t);
    d_bvec[n] = t;
}

// ---------------- weight convert: W [256k,256n] fp32 -> Wp [256n][hi(256)|lo(256)] bf16 ----
__global__ void k_wcvt(const float* __restrict__ W, bf16* __restrict__ Wp)
{
    int id = blockIdx.x * 256 + threadIdx.x;   // 65536
    int k = id >> 8, n = id & 255;
    float v = W[id];
    float hf, lf; bsplit(v, hf, lf);
    Wp[(size_t)n * 512 + k]       = __float2bfloat16(hf);
    Wp[(size_t)n * 512 + 256 + k] = __float2bfloat16(lf);
}

// ---------------- per-graph offsets via binary search (batch is sorted) ----------------
__global__ void k_off(const int* __restrict__ batch)
{
    int g = threadIdx.x;
    if (g > N_GRAPHS) return;
    if (g == N_GRAPHS) { d_off[N_GRAPHS] = N_NODES; return; }
    int lo = 0, hi = N_NODES;
    while (lo < hi) {
        int mid = (lo + hi) >> 1;
        if (batch[mid] < g) lo = mid + 1; else hi = mid;
    }
    d_off[g] = lo;
}

// ---------------- node embedding gather (pad rows -> 0) ----------------
__global__ void k_embed(const int* __restrict__ x, const float* __restrict__ Wn,
                        float* __restrict__ h)
{
    int gid = blockIdx.x * 256 + threadIdx.x;
    int n = gid >> 6;
    int c4 = (gid & 63) << 2;
    float4 v = make_float4(0.f, 0.f, 0.f, 0.f);
    if (n < N_NODES) v = *(const float4*)&Wn[(size_t)x[n] * 256 + c4];
    *(float4*)&h[(size_t)n * 256 + c4] = v;
}

// ---------------- scatter: agg[dst] += relu(h[src] + e)  (v4 float atomics) ----------------
__global__ void k_scatter(const int* __restrict__ ei, const float* __restrict__ e,
                          const float* __restrict__ h, float* __restrict__ agg)
{
    int gid = blockIdx.x * 256 + threadIdx.x;
    int eid = gid >> 6;
    int c4 = (gid & 63) << 2;
    int src = ei[eid];
    int dst = ei[N_EDGES + eid];
    float4 hv = *(const float4*)&h[(size_t)src * 256 + c4];
    float4 ev = *(const float4*)&e[(size_t)eid * 256 + c4];
    float4 m;
    m.x = fmaxf(hv.x + ev.x, 0.f);
    m.y = fmaxf(hv.y + ev.y, 0.f);
    m.z = fmaxf(hv.z + ev.z, 0.f);
    m.w = fmaxf(hv.w + ev.w, 0.f);
    float* p = &agg[(size_t)dst * 256 + c4];
    asm volatile("red.global.add.v4.f32 [%0], {%1, %2, %3, %4};"
                 :: "l"(p), "f"(m.x), "f"(m.y), "f"(m.z), "f"(m.w) : "memory");
}

// ======================================================================
// bf16 HMMA GEMM, fused fp32->(hi,lo) split at staging, ldmatrix fragments.
//   C = epi(Arow @ W^T + bias), exact triple: hi*hi + lo*hi + hi*lo
// ALOAD: 0 plain A; 1 (1+eps)A+Aagg; 2 A row = relu(attr@Wc+bc).
// CTA 128x64, BK=32, 256 thr, 8 warps (4x2), warp tile 32x32.
// ======================================================================
#define TSTR 40
#define ATS  (128 * TSTR)
#define BTS  (64 * TSTR)
#define SSTG (2 * ATS + 2 * BTS)
#define SMEMB (2 * SSTG * 2 + 5120)

template<int ALOAD, int EPI>
__global__ __launch_bounds__(256, 2)
void gemm_bf4(const float* __restrict__ A, const float* __restrict__ Aagg,
              const float* __restrict__ epsp,
              const bf16* __restrict__ Wp, const float* __restrict__ bias,
              const float* __restrict__ eattr, const float* __restrict__ sscale,
              float* __restrict__ C)
{
    extern __shared__ __align__(16) bf16 sm[];
    float* smF = (float*)(sm + 2 * SSTG);
    const unsigned smb = (unsigned)__cvta_generic_to_shared(sm);

    const int tid  = threadIdx.x;
    const int wid  = tid >> 5, lane = tid & 31;
    const int wm   = wid >> 1, wn = wid & 1;
    const int g    = lane >> 2, q = lane & 3;
    const int n0   = blockIdx.x * 64;
    const size_t m0 = (size_t)blockIdx.y * 128;

    const int lrow = tid >> 1;
    const int c0   = (tid & 1) * 16;
    const int brow = tid >> 2;
    const int bcol = (tid & 3) * 8;

    // ldmatrix per-lane element offsets (in bf16 elems)
    const int aoff = (wm * 32 + (lane & 15)) * TSTR + ((lane >> 4) << 3);
    const int boff = (wn * 32 + (lane & 7) + ((lane >> 4) << 3)) * TSTR
                   + (((lane >> 3) & 1) << 3);

    float epsv = 1.0f;
    if constexpr (ALOAD == 1) epsv = 1.0f + *epsp;

    float at0 = 0.f, at1 = 0.f, at2 = 0.f, at3 = 0.f;
    if constexpr (ALOAD == 2) {
        for (int i = tid; i < 1280; i += 256)
            smF[i] = (i < 1024) ? d_Wc[i] : d_bc[i - 1024];
        float4 av = *(const float4*)(A + (m0 + lrow) * 4);
        at0 = av.x; at1 = av.y; at2 = av.z; at3 = av.w;
        __syncthreads();
    }

    const float* Ab = A + (m0 + lrow) * 256 + c0;
    const float* Gb = nullptr;
    if constexpr (ALOAD == 1) Gb = Aagg + (m0 + lrow) * 256 + c0;
    const bf16* Bb = Wp + (size_t)(n0 + brow) * 512 + bcol;

    float acc[2][4][4];
#pragma unroll
    for (int mt = 0; mt < 2; ++mt)
#pragma unroll
        for (int nt = 0; nt < 4; ++nt)
#pragma unroll
            for (int i = 0; i < 4; ++i) acc[mt][nt][i] = 0.f;

    float v[16];

    auto loadA = [&](int klog) {
        if constexpr (ALOAD == 2) {
#pragma unroll
            for (int j = 0; j < 16; ++j) {
                int col = klog + c0 + j;
                float s = smF[1024 + col];
                s = fmaf(at0, smF[col],       s);
                s = fmaf(at1, smF[256 + col], s);
                s = fmaf(at2, smF[512 + col], s);
                s = fmaf(at3, smF[768 + col], s);
                v[j] = fmaxf(s, 0.f);
            }
        } else {
#pragma unroll
            for (int j = 0; j < 4; ++j) {
                float4 f = *(const float4*)(Ab + klog + 4 * j);
                if constexpr (ALOAD == 1) {
                    float4 gv = *(const float4*)(Gb + klog + 4 * j);
                    f.x = fmaf(epsv, f.x, gv.x); f.y = fmaf(epsv, f.y, gv.y);
                    f.z = fmaf(epsv, f.z, gv.z); f.w = fmaf(epsv, f.w, gv.w);
                }
                v[4 * j] = f.x; v[4 * j + 1] = f.y; v[4 * j + 2] = f.z; v[4 * j + 3] = f.w;
            }
        }
    };
    auto cpB = [&](int klog, int buf) {
        bf16* base = sm + buf * SSTG + 2 * ATS;
        cp16(base + brow * TSTR + bcol,       Bb + klog);
        cp16(base + BTS + brow * TSTR + bcol, Bb + 256 + klog);
        asm volatile("cp.async.commit_group;");
    };
    auto storeA = [&](int buf) {
        unsigned hp[8], lp[8];
#pragma unroll
        for (int i = 0; i < 8; ++i) {
            float h0, l0, h1, l1;
            bsplit(v[2 * i], h0, l0); bsplit(v[2 * i + 1], h1, l1);
            hp[i] = bfpack(h0, h1); lp[i] = bfpack(l0, l1);
        }
        bf16* ah = sm + buf * SSTG + lrow * TSTR + c0;
        bf16* al = ah + ATS;
        *(uint4*)ah       = make_uint4(hp[0], hp[1], hp[2], hp[3]);
        *(uint4*)(ah + 8) = make_uint4(hp[4], hp[5], hp[6], hp[7]);
        *(uint4*)al       = make_uint4(lp[0], lp[1], lp[2], lp[3]);
        *(uint4*)(al + 8) = make_uint4(lp[4], lp[5], lp[6], lp[7]);
    };

#define MMA1(ACC, FA, B0, B1)                                              \
    asm volatile(                                                          \
        "mma.sync.aligned.m16n8k16.row.col.f32.bf16.bf16.f32 "            \
        "{%0,%1,%2,%3}, {%4,%5,%6,%7}, {%8,%9}, {%0,%1,%2,%3};"           \
        : "+f"((ACC)[0]), "+f"((ACC)[1]), "+f"((ACC)[2]), "+f"((ACC)[3])  \
        : "r"((FA).x), "r"((FA).y), "r"((FA).z), "r"((FA).w),             \
          "r"(B0), "r"(B1))

    // ---- prologue ----
    loadA(0);
    cpB(0, 0);
    storeA(0);
    asm volatile("cp.async.wait_group 0;" ::: "memory");
    __syncthreads();

#pragma unroll 1
    for (int it = 0; it < 8; ++it) {
        const int cur = it & 1, nxt = cur ^ 1;
        if (it < 7) {
            cpB((it + 1) * 32, nxt);
            loadA((it + 1) * 32);
        }
        const unsigned Ah = smb + 2 * (cur * SSTG);
        const unsigned Bh = smb + 2 * (cur * SSTG + 2 * ATS);
#pragma unroll
        for (int ks = 0; ks < 2; ++ks) {
            const int kk = ks * 16;
            uint4 fa[2][2], fb[2][2];
#pragma unroll
            for (int mt = 0; mt < 2; ++mt) {
                unsigned ad = Ah + 2 * (aoff + mt * 16 * TSTR + kk);
                fa[0][mt] = ldsm4(ad);                 // Ahi
                fa[1][mt] = ldsm4(ad + 2 * ATS);       // Alo
            }
#pragma unroll
            for (int p = 0; p < 2; ++p) {
                unsigned bd = Bh + 2 * (boff + p * 16 * TSTR + kk);
                fb[0][p] = ldsm4(bd);                  // Bhi
                fb[1][p] = ldsm4(bd + 2 * BTS);        // Blo
            }
            // sub-passes: (Ah,Bh), (Al,Bh), (Ah,Bl)
#pragma unroll
            for (int s = 0; s < 3; ++s) {
                const int as = (s == 1) ? 1 : 0;
                const int bs = (s == 2) ? 1 : 0;
#pragma unroll
                for (int mt = 0; mt < 2; ++mt)
#pragma unroll
                    for (int p = 0; p < 2; ++p) {
                        MMA1(acc[mt][2 * p],     fa[as][mt], fb[bs][p].x, fb[bs][p].y);
                        MMA1(acc[mt][2 * p + 1], fa[as][mt], fb[bs][p].z, fb[bs][p].w);
                    }
            }
        }
        if (it < 7) {
            storeA(nxt);
            asm volatile("cp.async.wait_group 0;" ::: "memory");
        }
        __syncthreads();
    }
#undef MMA1

    // ---- epilogue ----
    const float sval = (EPI == 2) ? *sscale : 1.f;
#pragma unroll
    for (int mt = 0; mt < 2; ++mt) {
        size_t r0 = m0 + wm * 32 + mt * 16 + g;
        size_t r1 = r0 + 8;
        float s0 = 1.f, s1 = 1.f;
        if (EPI == 2) {
            s0 = (eattr[r0 * 4 + 1] > 0.f) ? sval : 1.f;
            s1 = (eattr[r1 * 4 + 1] > 0.f) ? sval : 1.f;
        }
#pragma unroll
        for (int nt = 0; nt < 4; ++nt) {
            int c = n0 + wn * 32 + nt * 8 + 2 * q;
            float b0 = bias[c], b1 = bias[c + 1];
            float v00 = acc[mt][nt][0] + b0;
            float v01 = acc[mt][nt][1] + b1;
            float v10 = acc[mt][nt][2] + b0;
            float v11 = acc[mt][nt][3] + b1;
            if (EPI == 1) {
                v00 = fmaxf(v00, 0.f); v01 = fmaxf(v01, 0.f);
                v10 = fmaxf(v10, 0.f); v11 = fmaxf(v11, 0.f);
            } else if (EPI == 2) {
                v00 *= s0; v01 *= s0; v10 *= s1; v11 *= s1;
            }
            *(float2*)&C[r0 * 256 + c] = make_float2(v00, v01);
            *(float2*)&C[r1 * 256 + c] = make_float2(v10, v11);
        }
    }
}

// ---------------- GraphNorm (in place), 2-pass, optional pooled-mean emit ----------------
__global__ void k_gnorm(float* __restrict__ h, const float* __restrict__ gamma,
                        const float* __restrict__ beta, const float* __restrict__ alpha,
                        int last)
{
    int g = blockIdx.x, c = threadIdx.x;
    int s = d_off[g], e = d_off[g + 1];
    int cnt = e - s;
    float inv = 1.0f / (float)(cnt > 0 ? cnt : 1);

    float s1 = 0.f, s2 = 0.f;
    for (int n = s; n < e; ++n) {
        float x = h[(size_t)n * 256 + c];
        s1 += x;
        s2 = fmaf(x, x, s2);
    }
    float mean = s1 * inv;
    float am = alpha[c] * mean;
    float var = s2 * inv - 2.f * am * mean + am * am;

    float sc = gamma[c] * rsqrtf(var + 1e-5f);
    float bt = beta[c];
    float gs = 0.f;
    for (int n = s; n < e; ++n) {
        float o = (h[(size_t)n * 256 + c] - am) * sc + bt;
        h[(size_t)n * 256 + c] = o;
        gs += o;
    }
    if (last) d_gm[g * 256 + c] = gs * inv;
}

// ---------------- head ----------------
__global__ void k_head(const float* __restrict__ W1, const float* __restrict__ W2,
                       const float* __restrict__ b2, float* __restrict__ out)
{
    __shared__ float gs[256];
    __shared__ float red[256];
    int g = blockIdx.x, n = threadIdx.x;
    gs[n] = d_gm[g * 256 + n];
    __syncthreads();
    float s = d_bvec[n];
#pragma unroll 8
    for (int k = 0; k < 256; ++k)
        s = fmaf(gs[k], W1[(size_t)k * 256 + n], s);
    red[n] = fmaxf(s, 0.f) * W2[n];
    __syncthreads();
    for (int st = 128; st > 0; st >>= 1) {
        if (n < st) red[n] += red[n + st];
        __syncthreads();
    }
    if (n == 0) out[g] = red[0] + b2[0];
}

// ---------------- launch ----------------
extern "C" void kernel_launch(void* const* d_in, const int* in_sizes, int n_in,
                              void* d_out, int out_size)
{
    const int*   x     = (const int*)d_in[0];
    const int*   ei    = (const int*)d_in[1];
    const float* attr  = (const float*)d_in[2];
    const int*   batch = (const int*)d_in[3];
    const float* nodeW = (const float*)d_in[4];
    const float* eW    = (const float*)d_in[5];
    const float* eb    = (const float*)d_in[6];
    const float* mW1   = (const float*)d_in[7];
    const float* mb1   = (const float*)d_in[8];
    const float* mW2   = (const float*)d_in[9];
    const float* mb2   = (const float*)d_in[10];
    const float* ss    = (const float*)d_in[11];
    const float* cW1   = (const float*)d_in[12];
    const float* cb1   = (const float*)d_in[13];
    const float* cW2   = (const float*)d_in[14];
    const float* cb2   = (const float*)d_in[15];
    const float* ceps  = (const float*)d_in[16];
    const float* ngam  = (const float*)d_in[17];
    const float* nbet  = (const float*)d_in[18];
    const float* nalp  = (const float*)d_in[19];
    const float* bio   = (const float*)d_in[20];
    const float* hW1   = (const float*)d_in[21];
    const float* hb1   = (const float*)d_in[22];
    const float* hW2   = (const float*)d_in[23];
    const float* hb2   = (const float*)d_in[24];
    float* out = (float*)d_out;

    float *e, *h, *agg, *t2;
    bf16 *Wp;
    cudaGetSymbolAddress((void**)&e,   d_e);
    cudaGetSymbolAddress((void**)&h,   d_h);
    cudaGetSymbolAddress((void**)&agg, d_agg);
    cudaGetSymbolAddress((void**)&t2,  d_t2);
    cudaGetSymbolAddress((void**)&Wp,  d_Wp);

    cudaFuncSetAttribute(gemm_bf4<2,2>, cudaFuncAttributeMaxDynamicSharedMemorySize, SMEMB);
    cudaFuncSetAttribute(gemm_bf4<1,1>, cudaFuncAttributeMaxDynamicSharedMemorySize, SMEMB);
    cudaFuncSetAttribute(gemm_bf4<0,0>, cudaFuncAttributeMaxDynamicSharedMemorySize, SMEMB);

    const size_t WSTRIDE = (size_t)256 * 512;

    k_pre<<<1, 256>>>(eW, eb, mW1, mb1, bio, hW1, hb1);
    k_off<<<1, N_GRAPHS + 1>>>(batch);
    k_wcvt<<<256, 256>>>(mW2, Wp);
    for (int l = 0; l < LAYERS; ++l) {
        k_wcvt<<<256, 256>>>(cW1 + (size_t)l * 65536, Wp + (1 + l) * WSTRIDE);
        k_wcvt<<<256, 256>>>(cW2 + (size_t)l * 65536, Wp + (4 + l) * WSTRIDE);
    }
    k_embed<<<N_PAD / 4, 256>>>(x, nodeW, h);

    gemm_bf4<2,2><<<dim3(4, N_EDGES / 128), 256, SMEMB>>>(
        attr, nullptr, nullptr, Wp, mb2, attr, ss, e);

    for (int l = 0; l < LAYERS; ++l) {
        cudaMemsetAsync(agg, 0, (size_t)N_PAD * 256 * sizeof(float), 0);
        k_scatter<<<N_EDGES / 4, 256>>>(ei, e, h, agg);
        gemm_bf4<1,1><<<dim3(4, N_PAD / 128), 256, SMEMB>>>(
            h, agg, ceps + l, Wp + (1 + l) * WSTRIDE, cb1 + (size_t)l * 256,
            nullptr, nullptr, t2);
        gemm_bf4<0,0><<<dim3(4, N_PAD / 128), 256, SMEMB>>>(
            t2, nullptr, nullptr, Wp + (4 + l) * WSTRIDE, cb2 + (size_t)l * 256,
            nullptr, nullptr, h);
        k_gnorm<<<N_GRAPHS, 256>>>(h, ngam + (size_t)l * 256, nbet + (size_t)l * 256,
                                   nalp + (size_t)l * 256, l == LAYERS - 1);
    }
    k_head<<<N_GRAPHS, 256>>>(hW1, hW2, hb2, out);
}